// round 6
// baseline (speedup 1.0000x reference)
#include <cuda_runtime.h>
#include <cuda_fp16.h>
#include <cstdint>

// Q4 group-quantized linear: out = x @ W^T + bias  (harness promotes fp16 -> fp32)
// NOTE: toolchain targets compute_103 (no 'a') => tcgen05 is NOT available.
// Strategy: fused dequant GEMM on mma.sync (HMMA), tuned for smem bandwidth:
//   preprocess x->fp16 / qw->packed bytes / (s,z)->half2
//   CTA tile 128x256, BK=64, 8 warps (2x4) of 64x64, 2-stage cp.async pipeline.

#define M_TOTAL 8192
#define K_TOTAL 4096
#define N_TOTAL 11008
#define BM 128
#define BN 256
#define BK 64
#define NKT (K_TOTAL / BK)         // 64
#define LDS 72                     // halves per smem row (144B stride, conflict-free)
#define A_STAGE_H (BM * LDS)       // 9216 halves
#define B_STAGE_H (BN * LDS)       // 18432 halves
#define SMEM_BYTES ((2 * A_STAGE_H + 2 * B_STAGE_H) * 2)   // 110592 B
#define N_GROUPS 352256

// ---- scratch (device globals; no runtime allocation) ----
__device__ __align__(16) __half  g_x16[(size_t)M_TOTAL * K_TOTAL];        // 64 MB
__device__ __align__(16) uint8_t g_qw8[(size_t)N_TOTAL * (K_TOTAL / 2)];  // 22.5 MB
__device__ __align__(4)  __half2 g_sz[N_GROUPS];                          // (scale, zero)

// ---- preprocess kernels ----
__global__ void convert_x_kernel(const float* __restrict__ x) {
    size_t base = ((size_t)blockIdx.x * blockDim.x + threadIdx.x) * 8;
    float4 a = *(const float4*)&x[base];
    float4 b = *(const float4*)&x[base + 4];
    __half2 h[4] = { __floats2half2_rn(a.x, a.y), __floats2half2_rn(a.z, a.w),
                     __floats2half2_rn(b.x, b.y), __floats2half2_rn(b.z, b.w) };
    *(uint4*)&g_x16[base] = *(uint4*)h;
}
__global__ void repack_qw_kernel(const int* __restrict__ qw) {
    size_t idx = (size_t)blockIdx.x * blockDim.x + threadIdx.x;
    int4 v = ((const int4*)qw)[idx];
    ((uint32_t*)g_qw8)[idx] = (uint32_t)(v.x & 0xFF) | ((uint32_t)(v.y & 0xFF) << 8) |
                              ((uint32_t)(v.z & 0xFF) << 16) | ((uint32_t)(v.w & 0xFF) << 24);
}
__global__ void pack_sz_kernel(const float* __restrict__ s, const float* __restrict__ z) {
    int i = blockIdx.x * blockDim.x + threadIdx.x;
    g_sz[i] = __floats2half2_rn(s[i], z[i]);
}

// dequant 4 packed bytes (8 nibbles) -> 4 half2: w = (n-8)*s + z
__device__ __forceinline__ void dq4(uint32_t v, __half2 s2, __half2 z2, __half2 k1032,
                                    __half2* o) {
    uint32_t b0 = 0x64006400u | (v & 0xFu)         | ((v & 0xF0u) << 12);
    uint32_t b1 = 0x64006400u | ((v >> 8) & 0xFu)  | ((v & 0xF000u) << 4);
    uint32_t b2 = 0x64006400u | ((v >> 16) & 0xFu) | ((v & 0xF00000u) >> 4);
    uint32_t b3 = 0x64006400u | ((v >> 24) & 0xFu) | ((v & 0xF0000000u) >> 12);
    o[0] = __hfma2(__hsub2(*(__half2*)&b0, k1032), s2, z2);
    o[1] = __hfma2(__hsub2(*(__half2*)&b1, k1032), s2, z2);
    o[2] = __hfma2(__hsub2(*(__half2*)&b2, k1032), s2, z2);
    o[3] = __hfma2(__hsub2(*(__half2*)&b3, k1032), s2, z2);
}

__global__ __launch_bounds__(256, 1)
void q4gemm_kernel(const float* __restrict__ scales_unused,
                   const float* __restrict__ bias,
                   float*       __restrict__ out)
{
    extern __shared__ __half smem[];
    __half* sA = smem;                        // [2][BM][LDS]
    __half* sB = smem + 2 * A_STAGE_H;        // [2][BN][LDS]

    const int tid  = threadIdx.x;
    const int wid  = tid >> 5;
    const int lane = tid & 31;
    const int warp_m = wid & 1;               // 0..1  (64 rows each)
    const int warp_n = wid >> 1;              // 0..3  (64 cols each)
    const int m0 = blockIdx.y * BM;
    const int n0 = blockIdx.x * BN;

    float acc[4][8][4];
    #pragma unroll
    for (int mi = 0; mi < 4; ++mi)
        #pragma unroll
        for (int ni = 0; ni < 8; ++ni)
            #pragma unroll
            for (int r = 0; r < 4; ++r)
                acc[mi][ni][r] = 0.0f;

    // B dequant role: one thread per B row (256 rows), 32 bytes (64 weights) each
    const __half2 k1032 = __floats2half2_rn(1032.0f, 1032.0f);
    const uint8_t* qrow = g_qw8 + (size_t)(n0 + tid) * (K_TOTAL / 2);
    const int gbase = (n0 + tid) * (K_TOTAL / 128);

    auto issue_a = [&](int kt, int st) {
        const __half* src_base = g_x16 + (size_t)m0 * K_TOTAL + kt * BK;
        __half* dst_base = sA + st * A_STAGE_H;
        #pragma unroll
        for (int i = 0; i < 4; ++i) {
            int u = tid + i * 256;          // 16B chunk 0..1023
            int r = u >> 3;
            int c = (u & 7) << 3;
            uint32_t daddr = (uint32_t)__cvta_generic_to_shared(dst_base + r * LDS + c);
            const __half* gsrc = src_base + (size_t)r * K_TOTAL + c;
            asm volatile("cp.async.cg.shared.global [%0], [%1], 16;"
                         :: "r"(daddr), "l"(gsrc));
        }
        asm volatile("cp.async.commit_group;");
    };

    auto dequant_store = [&](int kt, int st, uint4 v0, uint4 v1) {
        __half2 sz = g_sz[gbase + (kt >> 1)];
        __half2 s2 = __half2half2(__low2half(sz));
        __half2 z2 = __half2half2(__high2half(sz));
        __half2 hb[32];
        dq4(v0.x, s2, z2, k1032, hb + 0);
        dq4(v0.y, s2, z2, k1032, hb + 4);
        dq4(v0.z, s2, z2, k1032, hb + 8);
        dq4(v0.w, s2, z2, k1032, hb + 12);
        dq4(v1.x, s2, z2, k1032, hb + 16);
        dq4(v1.y, s2, z2, k1032, hb + 20);
        dq4(v1.z, s2, z2, k1032, hb + 24);
        dq4(v1.w, s2, z2, k1032, hb + 28);
        __half* dst = sB + st * B_STAGE_H + tid * LDS;
        #pragma unroll
        for (int q = 0; q < 8; ++q)
            *(uint4*)(dst + q * 8) = *(uint4*)(hb + q * 4);
    };

    // ---- prologue ----
    issue_a(0, 0);
    {
        uint4 v0 = *(const uint4*)(qrow);
        uint4 v1 = *(const uint4*)(qrow + 16);
        dequant_store(0, 0, v0, v1);
    }
    asm volatile("cp.async.wait_group 0;");
    __syncthreads();

    for (int kt = 0; kt < NKT; ++kt) {
        const int cur = kt & 1;
        const int nxt = cur ^ 1;

        uint4 v0, v1;
        if (kt + 1 < NKT) {
            issue_a(kt + 1, nxt);
            const uint8_t* qp = qrow + (size_t)(kt + 1) * (BK / 2);
            v0 = *(const uint4*)qp;
            v1 = *(const uint4*)(qp + 16);
        }

        const __half* cA = sA + cur * A_STAGE_H;
        const __half* cB = sB + cur * B_STAGE_H;

        #pragma unroll
        for (int ks = 0; ks < 4; ++ks) {
            uint32_t af[4][4];
            uint32_t bf[8][2];
            #pragma unroll
            for (int mi = 0; mi < 4; ++mi) {
                int row = warp_m * 64 + mi * 16 + (lane & 15);
                int col = ks * 16 + ((lane >> 4) << 3);
                uint32_t addr = (uint32_t)__cvta_generic_to_shared(cA + row * LDS + col);
                asm volatile(
                    "ldmatrix.sync.aligned.m8n8.x4.shared.b16 {%0,%1,%2,%3}, [%4];"
                    : "=r"(af[mi][0]), "=r"(af[mi][1]), "=r"(af[mi][2]), "=r"(af[mi][3])
                    : "r"(addr));
            }
            // B: ldmatrix.x4 loads two n-tiles (ni, ni+1) x two k-halves at once
            #pragma unroll
            for (int np = 0; np < 4; ++np) {
                int msel = lane >> 3;               // 0..3
                int row = warp_n * 64 + np * 16 + ((msel >> 1) << 3) + (lane & 7);
                int col = ks * 16 + ((msel & 1) << 3);
                uint32_t addr = (uint32_t)__cvta_generic_to_shared(cB + row * LDS + col);
                asm volatile(
                    "ldmatrix.sync.aligned.m8n8.x4.shared.b16 {%0,%1,%2,%3}, [%4];"
                    : "=r"(bf[np * 2][0]),     "=r"(bf[np * 2][1]),
                      "=r"(bf[np * 2 + 1][0]), "=r"(bf[np * 2 + 1][1])
                    : "r"(addr));
            }
            #pragma unroll
            for (int mi = 0; mi < 4; ++mi)
                #pragma unroll
                for (int ni = 0; ni < 8; ++ni)
                    asm volatile(
                        "mma.sync.aligned.m16n8k16.row.col.f32.f16.f16.f32 "
                        "{%0,%1,%2,%3}, {%4,%5,%6,%7}, {%8,%9}, {%0,%1,%2,%3};"
                        : "+f"(acc[mi][ni][0]), "+f"(acc[mi][ni][1]),
                          "+f"(acc[mi][ni][2]), "+f"(acc[mi][ni][3])
                        : "r"(af[mi][0]), "r"(af[mi][1]), "r"(af[mi][2]), "r"(af[mi][3]),
                          "r"(bf[ni][0]), "r"(bf[ni][1]));
        }

        if (kt + 1 < NKT) {
            dequant_store(kt + 1, nxt, v0, v1);
            asm volatile("cp.async.wait_group 0;");
        }
        __syncthreads();
    }

    // ---- epilogue: bias + fp16 rounding (match reference), fp32 store ----
    #pragma unroll
    for (int mi = 0; mi < 4; ++mi) {
        #pragma unroll
        for (int ni = 0; ni < 8; ++ni) {
            int m = m0 + warp_m * 64 + mi * 16 + (lane >> 2);
            int n = n0 + warp_n * 64 + ni * 8 + (lane & 3) * 2;
            float b0 = bias[n];
            float b1 = bias[n + 1];
            float2 r0 = make_float2(__half2float(__float2half(acc[mi][ni][0] + b0)),
                                    __half2float(__float2half(acc[mi][ni][1] + b1)));
            float2 r1 = make_float2(__half2float(__float2half(acc[mi][ni][2] + b0)),
                                    __half2float(__float2half(acc[mi][ni][3] + b1)));
            *(float2*)&out[(size_t)m * N_TOTAL + n]       = r0;
            *(float2*)&out[(size_t)(m + 8) * N_TOTAL + n] = r1;
        }
    }
}

extern "C" void kernel_launch(void* const* d_in, const int* in_sizes, int n_in,
                              void* d_out, int out_size)
{
    const float* x      = (const float*)d_in[0];
    const int*   qw     = (const int*)  d_in[1];
    const float* scales = (const float*)d_in[2];
    const float* zeros  = (const float*)d_in[3];
    const float* bias   = (const float*)d_in[4];
    float*       out    = (float*)d_out;

    cudaFuncSetAttribute(q4gemm_kernel,
                         cudaFuncAttributeMaxDynamicSharedMemorySize, SMEM_BYTES);

    convert_x_kernel<<<(M_TOTAL * (size_t)K_TOTAL) / 8 / 256, 256>>>(x);
    repack_qw_kernel<<<22544384 / 4 / 256, 256>>>(qw);
    pack_sz_kernel<<<N_GROUPS / 256, 256>>>(scales, zeros);

    dim3 grid(N_TOTAL / BN, M_TOTAL / BM);   // 43 x 64
    q4gemm_kernel<<<grid, 256, SMEM_BYTES>>>(scales, bias, out);
}

// round 7
// speedup vs baseline: 1.0823x; 1.0823x over previous
#include <cuda_runtime.h>
#include <cuda_fp16.h>
#include <cstdint>

// Q4 group-quantized linear: out = x @ W^T + bias  (harness promotes fp16 -> fp32)
// compute_103 toolchain => no tcgen05; HMMA mma.sync path.
// R7: CTA 128x256, BK=64, 512 threads (16 warps, 2x8, warp tile 64x32),
//     2-stage cp.async pipeline, LOP3/HFMA2 dequant, preprocessed inputs.

#define M_TOTAL 8192
#define K_TOTAL 4096
#define N_TOTAL 11008
#define BM 128
#define BN 256
#define BK 64
#define NKT (K_TOTAL / BK)         // 64
#define LDS 72                     // halves per smem row (144B stride, conflict-free)
#define A_STAGE_H (BM * LDS)       // 9216 halves
#define B_STAGE_H (BN * LDS)       // 18432 halves
#define SMEM_BYTES ((2 * A_STAGE_H + 2 * B_STAGE_H) * 2)   // 110592 B
#define N_GROUPS 352256

// ---- scratch (device globals; no runtime allocation) ----
__device__ __align__(16) __half  g_x16[(size_t)M_TOTAL * K_TOTAL];        // 64 MB
__device__ __align__(16) uint8_t g_qw8[(size_t)N_TOTAL * (K_TOTAL / 2)];  // 22.5 MB
__device__ __align__(4)  __half2 g_sz[N_GROUPS];                          // (scale, zero)

// ---- preprocess kernels ----
__global__ void convert_x_kernel(const float* __restrict__ x) {
    size_t base = ((size_t)blockIdx.x * blockDim.x + threadIdx.x) * 8;
    float4 a = *(const float4*)&x[base];
    float4 b = *(const float4*)&x[base + 4];
    __half2 h[4] = { __floats2half2_rn(a.x, a.y), __floats2half2_rn(a.z, a.w),
                     __floats2half2_rn(b.x, b.y), __floats2half2_rn(b.z, b.w) };
    *(uint4*)&g_x16[base] = *(uint4*)h;
}
__global__ void repack_qw_kernel(const int* __restrict__ qw) {
    size_t idx = (size_t)blockIdx.x * blockDim.x + threadIdx.x;
    int4 v = ((const int4*)qw)[idx];
    ((uint32_t*)g_qw8)[idx] = (uint32_t)(v.x & 0xFF) | ((uint32_t)(v.y & 0xFF) << 8) |
                              ((uint32_t)(v.z & 0xFF) << 16) | ((uint32_t)(v.w & 0xFF) << 24);
}
__global__ void pack_sz_kernel(const float* __restrict__ s, const float* __restrict__ z) {
    int i = blockIdx.x * blockDim.x + threadIdx.x;
    g_sz[i] = __floats2half2_rn(s[i], z[i]);
}

// dequant 4 packed bytes (8 nibbles) -> 4 half2: w = (n-8)*s + z
__device__ __forceinline__ void dq4(uint32_t v, __half2 s2, __half2 z2, __half2 k1032,
                                    __half2* o) {
    uint32_t b0 = 0x64006400u | (v & 0xFu)         | ((v & 0xF0u) << 12);
    uint32_t b1 = 0x64006400u | ((v >> 8) & 0xFu)  | ((v & 0xF000u) << 4);
    uint32_t b2 = 0x64006400u | ((v >> 16) & 0xFu) | ((v & 0xF00000u) >> 4);
    uint32_t b3 = 0x64006400u | ((v >> 24) & 0xFu) | ((v & 0xF0000000u) >> 12);
    o[0] = __hfma2(__hsub2(*(__half2*)&b0, k1032), s2, z2);
    o[1] = __hfma2(__hsub2(*(__half2*)&b1, k1032), s2, z2);
    o[2] = __hfma2(__hsub2(*(__half2*)&b2, k1032), s2, z2);
    o[3] = __hfma2(__hsub2(*(__half2*)&b3, k1032), s2, z2);
}

__global__ __launch_bounds__(512, 1)
void q4gemm_kernel(const float* __restrict__ bias,
                   float*       __restrict__ out)
{
    extern __shared__ __half smem[];
    __half* sA = smem;                        // [2][BM][LDS]
    __half* sB = smem + 2 * A_STAGE_H;        // [2][BN][LDS]

    const int tid  = threadIdx.x;
    const int wid  = tid >> 5;                // 0..15
    const int lane = tid & 31;
    const int warp_m = wid & 1;               // 0..1 (64 rows)
    const int warp_n = wid >> 1;              // 0..7 (32 cols)
    const int m0 = blockIdx.y * BM;
    const int n0 = blockIdx.x * BN;

    float acc[4][4][4];
    #pragma unroll
    for (int mi = 0; mi < 4; ++mi)
        #pragma unroll
        for (int ni = 0; ni < 4; ++ni)
            #pragma unroll
            for (int r = 0; r < 4; ++r)
                acc[mi][ni][r] = 0.0f;

    // B dequant role: 2 threads per row (256 rows), 16 bytes (32 weights) each
    const int br = tid >> 1;
    const int bh = tid & 1;
    const __half2 k1032 = __floats2half2_rn(1032.0f, 1032.0f);
    const uint8_t* qrow = g_qw8 + (size_t)(n0 + br) * (K_TOTAL / 2) + bh * 16;
    const int gbase = (n0 + br) * (K_TOTAL / 128);

    auto issue_a = [&](int kt, int st) {
        const __half* src_base = g_x16 + (size_t)m0 * K_TOTAL + kt * BK;
        __half* dst_base = sA + st * A_STAGE_H;
        #pragma unroll
        for (int i = 0; i < 2; ++i) {
            int u = tid + i * 512;          // 16B chunk 0..1023
            int r = u >> 3;
            int c = (u & 7) << 3;
            uint32_t daddr = (uint32_t)__cvta_generic_to_shared(dst_base + r * LDS + c);
            const __half* gsrc = src_base + (size_t)r * K_TOTAL + c;
            asm volatile("cp.async.cg.shared.global [%0], [%1], 16;"
                         :: "r"(daddr), "l"(gsrc));
        }
        asm volatile("cp.async.commit_group;");
    };

    auto dequant_store = [&](int kt, int st, uint4 qv) {
        __half2 sz = g_sz[gbase + (kt >> 1)];
        __half2 s2 = __half2half2(__low2half(sz));
        __half2 z2 = __half2half2(__high2half(sz));
        __half2 hb[16];
        dq4(qv.x, s2, z2, k1032, hb + 0);
        dq4(qv.y, s2, z2, k1032, hb + 4);
        dq4(qv.z, s2, z2, k1032, hb + 8);
        dq4(qv.w, s2, z2, k1032, hb + 12);
        __half* dst = sB + st * B_STAGE_H + br * LDS + bh * 32;
        #pragma unroll
        for (int q = 0; q < 4; ++q)
            *(uint4*)(dst + q * 8) = *(uint4*)(hb + q * 4);
    };

    // ---- prologue ----
    issue_a(0, 0);
    dequant_store(0, 0, *(const uint4*)qrow);
    asm volatile("cp.async.wait_group 0;");
    __syncthreads();

    for (int kt = 0; kt < NKT; ++kt) {
        const int cur = kt & 1;
        const int nxt = cur ^ 1;

        uint4 qv;
        if (kt + 1 < NKT) {
            issue_a(kt + 1, nxt);
            qv = *(const uint4*)(qrow + (size_t)(kt + 1) * (BK / 2));
        }

        const __half* cA = sA + cur * A_STAGE_H;
        const __half* cB = sB + cur * B_STAGE_H;

        #pragma unroll
        for (int ks = 0; ks < 4; ++ks) {
            uint32_t af[4][4];
            uint32_t bf[4][2];
            #pragma unroll
            for (int mi = 0; mi < 4; ++mi) {
                int row = warp_m * 64 + mi * 16 + (lane & 15);
                int col = ks * 16 + ((lane >> 4) << 3);
                uint32_t addr = (uint32_t)__cvta_generic_to_shared(cA + row * LDS + col);
                asm volatile(
                    "ldmatrix.sync.aligned.m8n8.x4.shared.b16 {%0,%1,%2,%3}, [%4];"
                    : "=r"(af[mi][0]), "=r"(af[mi][1]), "=r"(af[mi][2]), "=r"(af[mi][3])
                    : "r"(addr));
            }
            // B: two x4 ldmatrix ops load 4 n-tiles (ni pairs) for this ks
            #pragma unroll
            for (int np = 0; np < 2; ++np) {
                int msel = lane >> 3;               // 0..3
                int row = warp_n * 32 + np * 16 + ((msel >> 1) << 3) + (lane & 7);
                int col = ks * 16 + ((msel & 1) << 3);
                uint32_t addr = (uint32_t)__cvta_generic_to_shared(cB + row * LDS + col);
                asm volatile(
                    "ldmatrix.sync.aligned.m8n8.x4.shared.b16 {%0,%1,%2,%3}, [%4];"
                    : "=r"(bf[np * 2][0]),     "=r"(bf[np * 2][1]),
                      "=r"(bf[np * 2 + 1][0]), "=r"(bf[np * 2 + 1][1])
                    : "r"(addr));
            }
            #pragma unroll
            for (int mi = 0; mi < 4; ++mi)
                #pragma unroll
                for (int ni = 0; ni < 4; ++ni)
                    asm volatile(
                        "mma.sync.aligned.m16n8k16.row.col.f32.f16.f16.f32 "
                        "{%0,%1,%2,%3}, {%4,%5,%6,%7}, {%8,%9}, {%0,%1,%2,%3};"
                        : "+f"(acc[mi][ni][0]), "+f"(acc[mi][ni][1]),
                          "+f"(acc[mi][ni][2]), "+f"(acc[mi][ni][3])
                        : "r"(af[mi][0]), "r"(af[mi][1]), "r"(af[mi][2]), "r"(af[mi][3]),
                          "r"(bf[ni][0]), "r"(bf[ni][1]));
        }

        if (kt + 1 < NKT) {
            dequant_store(kt + 1, nxt, qv);
            asm volatile("cp.async.wait_group 0;");
        }
        __syncthreads();
    }

    // ---- epilogue: bias + fp16 rounding (match reference), fp32 store ----
    #pragma unroll
    for (int mi = 0; mi < 4; ++mi) {
        #pragma unroll
        for (int ni = 0; ni < 4; ++ni) {
            int m = m0 + warp_m * 64 + mi * 16 + (lane >> 2);
            int n = n0 + warp_n * 32 + ni * 8 + (lane & 3) * 2;
            float b0 = bias[n];
            float b1 = bias[n + 1];
            float2 r0 = make_float2(__half2float(__float2half(acc[mi][ni][0] + b0)),
                                    __half2float(__float2half(acc[mi][ni][1] + b1)));
            float2 r1 = make_float2(__half2float(__float2half(acc[mi][ni][2] + b0)),
                                    __half2float(__float2half(acc[mi][ni][3] + b1)));
            *(float2*)&out[(size_t)m * N_TOTAL + n]       = r0;
            *(float2*)&out[(size_t)(m + 8) * N_TOTAL + n] = r1;
        }
    }
}

extern "C" void kernel_launch(void* const* d_in, const int* in_sizes, int n_in,
                              void* d_out, int out_size)
{
    const float* x      = (const float*)d_in[0];
    const int*   qw     = (const int*)  d_in[1];
    const float* scales = (const float*)d_in[2];
    const float* zeros  = (const float*)d_in[3];
    const float* bias   = (const float*)d_in[4];
    float*       out    = (float*)d_out;

    cudaFuncSetAttribute(q4gemm_kernel,
                         cudaFuncAttributeMaxDynamicSharedMemorySize, SMEM_BYTES);

    convert_x_kernel<<<(M_TOTAL * (size_t)K_TOTAL) / 8 / 256, 256>>>(x);
    repack_qw_kernel<<<22544384 / 4 / 256, 256>>>(qw);
    pack_sz_kernel<<<N_GROUPS / 256, 256>>>(scales, zeros);

    dim3 grid(N_TOTAL / BN, M_TOTAL / BM);   // 43 x 64
    q4gemm_kernel<<<grid, 512, SMEM_BYTES>>>(bias, out);
}

// round 8
// speedup vs baseline: 1.0861x; 1.0035x over previous
#include <cuda_runtime.h>
#include <cuda_fp16.h>
#include <cstdint>

// Q4 group-quantized linear: out = x @ W^T + bias (harness promotes fp16 -> fp32)
// compute_103 toolchain => no tcgen05; HMMA mma.sync path.
// R8: B never touches smem. Preprocess qweight into fragment-native u64 layout;
//     each thread dequants its own MMA B-fragments in registers (Marlin-style).
//     CTA 128x128, BK=64, 256 thr (8 warps 2x4, warp tile 64x32), A-only smem
//     double buffer (static, 37KB), 2 CTAs/SM.

#define M_TOTAL 8192
#define K_TOTAL 4096
#define N_TOTAL 11008
#define BM 128
#define BN 128
#define BK 64
#define NKT (K_TOTAL / BK)     // 64
#define LDS 72                 // halves per A smem row (conflict-free ldmatrix)
#define A_STAGE_H (BM * LDS)   // 9216 halves
#define N_GROUPS 352256

// ---- scratch (device globals; no runtime allocation) ----
__device__ __align__(16) __half             g_x16[(size_t)M_TOTAL * K_TOTAL];   // 64 MB
__device__ __align__(16) unsigned long long g_qt[(size_t)N_TOTAL * 256];        // 22.5 MB
__device__ __align__(4)  __half2            g_sz[N_GROUPS];                     // (s,z)

// ---- preprocess: fp32 x -> fp16 ----
__global__ void convert_x_kernel(const float* __restrict__ x) {
    size_t base = ((size_t)blockIdx.x * blockDim.x + threadIdx.x) * 8;
    float4 a = *(const float4*)&x[base];
    float4 b = *(const float4*)&x[base + 4];
    __half2 h[4] = { __floats2half2_rn(a.x, a.y), __floats2half2_rn(a.z, a.w),
                     __floats2half2_rn(b.x, b.y), __floats2half2_rn(b.z, b.w) };
    *(uint4*)&g_x16[base] = *(uint4*)h;
}

// ---- preprocess: qweight (int32-per-byte) -> fragment-native u64 layout ----
// One thread per (n, kt): reads the 32-byte k-slab (as 32 ints, 128B contiguous),
// emits 4 u64s: u64_j byte p = slab[j + 4p]. Thread lane j in the GEMM then gets,
// in word kp, bytes for k-steps (2kp, 2kp+1) already in b0/b1 fragment order.
__global__ void repack_qt_kernel(const int* __restrict__ qw) {
    int t = blockIdx.x * blockDim.x + threadIdx.x;     // 0 .. 704511
    size_t base = (size_t)(t >> 6) * 2048 + (t & 63) * 32;
    int w[32];
    const int4* p = (const int4*)(qw + base);
    #pragma unroll
    for (int q = 0; q < 8; ++q) {
        int4 v = p[q];
        w[4 * q] = v.x; w[4 * q + 1] = v.y; w[4 * q + 2] = v.z; w[4 * q + 3] = v.w;
    }
    #pragma unroll
    for (int j = 0; j < 4; ++j) {
        unsigned long long v = 0;
        #pragma unroll
        for (int pp = 0; pp < 8; ++pp)
            v |= (unsigned long long)(w[j + 4 * pp] & 0xFF) << (8 * pp);
        g_qt[(size_t)t * 4 + j] = v;
    }
}

__global__ void pack_sz_kernel(const float* __restrict__ s, const float* __restrict__ z) {
    int i = blockIdx.x * blockDim.x + threadIdx.x;
    g_sz[i] = __floats2half2_rn(s[i], z[i]);
}

// dequant 4 packed bytes -> 4 half2 = {b0(ksA), b1(ksA), b0(ksB), b1(ksB)}
__device__ __forceinline__ void dq4(uint32_t v, __half2 s2, __half2 z2, __half2 k1032,
                                    __half2* o) {
    uint32_t b0 = 0x64006400u | (v & 0xFu)         | ((v & 0xF0u) << 12);
    uint32_t b1 = 0x64006400u | ((v >> 8) & 0xFu)  | ((v & 0xF000u) << 4);
    uint32_t b2 = 0x64006400u | ((v >> 16) & 0xFu) | ((v & 0xF00000u) >> 4);
    uint32_t b3 = 0x64006400u | ((v >> 24) & 0xFu) | ((v & 0xF0000000u) >> 12);
    o[0] = __hfma2(__hsub2(*(__half2*)&b0, k1032), s2, z2);
    o[1] = __hfma2(__hsub2(*(__half2*)&b1, k1032), s2, z2);
    o[2] = __hfma2(__hsub2(*(__half2*)&b2, k1032), s2, z2);
    o[3] = __hfma2(__hsub2(*(__half2*)&b3, k1032), s2, z2);
}

__global__ __launch_bounds__(256, 2)
void q4gemm_kernel(const float* __restrict__ bias,
                   float*       __restrict__ out)
{
    __shared__ __half sA[2][A_STAGE_H];    // 36.9 KB static; B lives in registers

    const int tid  = threadIdx.x;
    const int wid  = tid >> 5;             // 0..7
    const int lane = tid & 31;
    const int warp_m = wid & 1;            // 0..1 (64 rows)
    const int warp_n = wid >> 1;           // 0..3 (32 cols)
    const int m0 = blockIdx.y * BM;
    const int n0 = blockIdx.x * BN;

    float acc[4][4][4];
    #pragma unroll
    for (int mi = 0; mi < 4; ++mi)
        #pragma unroll
        for (int ni = 0; ni < 4; ++ni)
            #pragma unroll
            for (int r = 0; r < 4; ++r)
                acc[mi][ni][r] = 0.0f;

    // B fragment sources: per ni, this thread covers n = n0 + warp_n*32 + ni*8 + (lane>>2)
    const int j4 = lane & 3;
    const __half2 k1032 = __floats2half2_rn(1032.0f, 1032.0f);
    const unsigned long long* qtp[4];
    int szb[4];
    #pragma unroll
    for (int ni = 0; ni < 4; ++ni) {
        int n = n0 + warp_n * 32 + ni * 8 + (lane >> 2);
        qtp[ni] = g_qt + (size_t)n * 256 + j4;
        szb[ni] = n * 32;
    }

    auto issue_a = [&](int kt, int st) {
        const __half* src_base = g_x16 + (size_t)m0 * K_TOTAL + kt * BK;
        #pragma unroll
        for (int i = 0; i < 4; ++i) {
            int u = tid + i * 256;          // 16B chunk 0..1023
            int r = u >> 3;
            int c = (u & 7) << 3;
            uint32_t daddr = (uint32_t)__cvta_generic_to_shared(&sA[st][r * LDS + c]);
            const __half* gsrc = src_base + (size_t)r * K_TOTAL + c;
            asm volatile("cp.async.cg.shared.global [%0], [%1], 16;"
                         :: "r"(daddr), "l"(gsrc));
        }
        asm volatile("cp.async.commit_group;");
    };

    // ---- prologue ----
    issue_a(0, 0);
    asm volatile("cp.async.wait_group 0;");
    __syncthreads();

    for (int kt = 0; kt < NKT; ++kt) {
        const int cur = kt & 1;
        const int nxt = cur ^ 1;
        if (kt + 1 < NKT) issue_a(kt + 1, nxt);

        // B: one u64 + one (s,z) per ni, straight from L2/L1
        unsigned long long bu[4];
        __half2 s2[4], z2[4];
        #pragma unroll
        for (int ni = 0; ni < 4; ++ni) {
            bu[ni] = qtp[ni][kt * 4];
            __half2 sz = g_sz[szb[ni] + (kt >> 1)];
            s2[ni] = __half2half2(__low2half(sz));
            z2[ni] = __half2half2(__high2half(sz));
        }

        const __half* cA = sA[cur];
        #pragma unroll
        for (int kp = 0; kp < 2; ++kp) {
            __half2 bf[4][4];
            #pragma unroll
            for (int ni = 0; ni < 4; ++ni)
                dq4((uint32_t)(bu[ni] >> (32 * kp)), s2[ni], z2[ni], k1032, bf[ni]);

            #pragma unroll
            for (int ks2 = 0; ks2 < 2; ++ks2) {
                const int ks = kp * 2 + ks2;
                uint32_t af[4][4];
                #pragma unroll
                for (int mi = 0; mi < 4; ++mi) {
                    int row = warp_m * 64 + mi * 16 + (lane & 15);
                    int col = ks * 16 + ((lane >> 4) << 3);
                    uint32_t addr = (uint32_t)__cvta_generic_to_shared(cA + row * LDS + col);
                    asm volatile(
                        "ldmatrix.sync.aligned.m8n8.x4.shared.b16 {%0,%1,%2,%3}, [%4];"
                        : "=r"(af[mi][0]), "=r"(af[mi][1]),
                          "=r"(af[mi][2]), "=r"(af[mi][3])
                        : "r"(addr));
                }
                #pragma unroll
                for (int mi = 0; mi < 4; ++mi)
                    #pragma unroll
                    for (int ni = 0; ni < 4; ++ni)
                        asm volatile(
                            "mma.sync.aligned.m16n8k16.row.col.f32.f16.f16.f32 "
                            "{%0,%1,%2,%3}, {%4,%5,%6,%7}, {%8,%9}, {%0,%1,%2,%3};"
                            : "+f"(acc[mi][ni][0]), "+f"(acc[mi][ni][1]),
                              "+f"(acc[mi][ni][2]), "+f"(acc[mi][ni][3])
                            : "r"(af[mi][0]), "r"(af[mi][1]),
                              "r"(af[mi][2]), "r"(af[mi][3]),
                              "r"(*(const uint32_t*)&bf[ni][2 * ks2]),
                              "r"(*(const uint32_t*)&bf[ni][2 * ks2 + 1]));
            }
        }

        if (kt + 1 < NKT) asm volatile("cp.async.wait_group 0;");
        __syncthreads();
    }

    // ---- epilogue: bias + fp16 rounding (match reference), fp32 store ----
    #pragma unroll
    for (int mi = 0; mi < 4; ++mi) {
        #pragma unroll
        for (int ni = 0; ni < 4; ++ni) {
            int m = m0 + warp_m * 64 + mi * 16 + (lane >> 2);
            int n = n0 + warp_n * 32 + ni * 8 + (lane & 3) * 2;
            float b0 = bias[n];
            float b1 = bias[n + 1];
            float2 r0 = make_float2(__half2float(__float2half(acc[mi][ni][0] + b0)),
                                    __half2float(__float2half(acc[mi][ni][1] + b1)));
            float2 r1 = make_float2(__half2float(__float2half(acc[mi][ni][2] + b0)),
                                    __half2float(__float2half(acc[mi][ni][3] + b1)));
            *(float2*)&out[(size_t)m * N_TOTAL + n]       = r0;
            *(float2*)&out[(size_t)(m + 8) * N_TOTAL + n] = r1;
        }
    }
}

extern "C" void kernel_launch(void* const* d_in, const int* in_sizes, int n_in,
                              void* d_out, int out_size)
{
    const float* x      = (const float*)d_in[0];
    const int*   qw     = (const int*)  d_in[1];
    const float* scales = (const float*)d_in[2];
    const float* zeros  = (const float*)d_in[3];
    const float* bias   = (const float*)d_in[4];
    float*       out    = (float*)d_out;

    convert_x_kernel<<<(M_TOTAL * (size_t)K_TOTAL) / 8 / 256, 256>>>(x);
    repack_qt_kernel<<<(N_TOTAL * 64) / 256, 256>>>(qw);   // 2752 blocks
    pack_sz_kernel<<<N_GROUPS / 256, 256>>>(scales, zeros);

    dim3 grid(N_TOTAL / BN, M_TOTAL / BM);   // 86 x 64
    q4gemm_kernel<<<grid, 256>>>(bias, out);
}